// round 5
// baseline (speedup 1.0000x reference)
#include <cuda_runtime.h>
#include <cstdint>

// ---------------------------------------------------------------------------
// pitch_predictor: 4x BiLSTM(H=16) over T=2048, B=128 -> downsample 7::8 ->
// 4x LSTM(H=1) over 256 steps. Latency-bound recurrences; one warp per chain.
// ---------------------------------------------------------------------------

#define Bn 128
#define Tn 2048
#define TU 256

// Scratch (device globals; no allocation allowed)
__device__ float g_xWp[2ull * Bn * Tn * 64];   // gate-permuted input projections, [dir][b][t][64]
__device__ float g_x[(size_t)Bn * Tn * 32];    // layer activations [b][t][32] (fwd 0..15, bwd 16..31)
__device__ float g_xu0[(size_t)Bn * TU * 4];   // upper layer-0 input projections

// ---- fast activations (ex2/rcp approx: rel err ~2^-22, far under 1e-3) ----
__device__ __forceinline__ float ex2f(float x) {
    float r; asm("ex2.approx.f32 %0, %1;" : "=f"(r) : "f"(x)); return r;
}
__device__ __forceinline__ float rcpf(float x) {
    float r; asm("rcp.approx.f32 %0, %1;" : "=f"(r) : "f"(x)); return r;
}
#define L2E 1.4426950408889634f
__device__ __forceinline__ float sigmf_(float x) { return rcpf(1.f + ex2f(-L2E * x)); }
__device__ __forceinline__ float tanhf_(float x) { return fmaf(2.f, rcpf(1.f + ex2f(-2.f * L2E * x)), -1.f); }

// ---------------------------------------------------------------------------
// Precompute xW for one bidir layer, both directions, permuted gate layout:
//   out[dir][bt][p],  p = 2*(r&31) + (r>>5)  for gate row r (i/f:0-31, g/o:32-63)
// so scan lane l reads float2 at p=2l: (row l, row 32+l).
// ---------------------------------------------------------------------------
template <int CIN>
__global__ void __launch_bounds__(256) precompute_bidir(
    const float* __restrict__ xin, int use_gx,
    const float* __restrict__ Wih,   // [2][64][CIN]
    const float* __restrict__ bias)  // [2][64]
{
    __shared__ float xs[32 * CIN];
    const float* x = use_gx ? (const float*)g_x : xin;
    const int r0 = blockIdx.x * 32;  // 32 consecutive (b*T+t) rows
    const float* src = x + (size_t)r0 * CIN;
    for (int i = threadIdx.x; i < 32 * CIN; i += 256) xs[i] = src[i];
    __syncthreads();

    const int p = threadIdx.x & 63;
    const int sub = threadIdx.x >> 6;                 // 0..3
    const int rw = ((p & 1) << 5) + (p >> 1);         // gate row for this p

    float w0[CIN], w1[CIN];
#pragma unroll
    for (int i = 0; i < CIN; i++) {
        w0[i] = Wih[rw * CIN + i];
        w1[i] = Wih[(64 + rw) * CIN + i];
    }
    const float b0 = bias[rw], b1 = bias[64 + rw];

#pragma unroll
    for (int rr = 0; rr < 8; rr++) {
        const int row = sub + rr * 4;  // 0..31
        const float* xr = xs + row * CIN;
        float a0 = b0, a1 = b1;
#pragma unroll
        for (int i = 0; i < CIN; i++) {
            const float xv = xr[i];
            a0 = fmaf(w0[i], xv, a0);
            a1 = fmaf(w1[i], xv, a1);
        }
        const size_t bt = (size_t)(r0 + row);
        g_xWp[bt * 64 + p] = a0;
        g_xWp[((size_t)Bn * Tn + bt) * 64 + p] = a1;
    }
}

// ---------------------------------------------------------------------------
// Bidirectional scan: one warp per (b, dir). Lane j<16 owns gates (i_j, g_j),
// lane j+16 owns (f_j, o_j). Both lanes of a pair compute identical (c_j,h_j).
// ---------------------------------------------------------------------------
__global__ void __launch_bounds__(32) scan_bidir(const float* __restrict__ Whh /* [2][64][16] */)
{
    const int b = blockIdx.x;
    const int dir = blockIdx.y;
    const int lane = threadIdx.x;
    const int hi = lane >> 4;

    const float* wb = Whh + dir * 64 * 16;
    float WA[16], WB[16];
#pragma unroll
    for (int k = 0; k < 16; k++) {
        WA[k] = wb[lane * 16 + k];        // row = lane    (i_j / f_j)
        WB[k] = wb[(32 + lane) * 16 + k]; // row = 32+lane (g_j / o_j)
    }
    // actB per-lane constants: lane<16 -> tanh, lane>=16 -> sigmoid
    const float mB = hi ? -L2E : -2.f * L2E;
    const float aB = hi ? 1.f : 2.f;
    const float cB = hi ? 0.f : -1.f;

    float h[16];
#pragma unroll
    for (int k = 0; k < 16; k++) h[k] = 0.f;
    float c = 0.f;

    const size_t chain = ((size_t)dir * Bn + b) * Tn;
    const float* pbase = g_xWp + chain * 64 + 2 * lane;
    const int tstart = dir ? (Tn - 1) : 0;
    const int tstep = dir ? -1 : 1;

    const int PF = 8;
    float2 buf[PF];
#pragma unroll
    for (int s = 0; s < PF; s++)
        buf[s] = *(const float2*)(pbase + (long)(tstart + s * tstep) * 64);

    float* outb = g_x + (size_t)b * Tn * 32 + dir * 16 + lane;  // lane<16 writes

    for (int it = 0; it < Tn; it += PF) {
#pragma unroll
        for (int s = 0; s < PF; s++) {
            const int st = it + s;
            const float2 xw = buf[s];
            const int pt = st + PF;
            if (pt < Tn)
                buf[s] = *(const float2*)(pbase + (long)(tstart + pt * tstep) * 64);

            // two 16-dots, split accumulators to halve FMA chain depth
            float a0 = xw.x, a1 = 0.f, d0 = xw.y, d1 = 0.f;
#pragma unroll
            for (int k = 0; k < 8; k++) {
                a0 = fmaf(WA[k], h[k], a0);
                d0 = fmaf(WB[k], h[k], d0);
            }
#pragma unroll
            for (int k = 8; k < 16; k++) {
                a1 = fmaf(WA[k], h[k], a1);
                d1 = fmaf(WB[k], h[k], d1);
            }
            const float preA = a0 + a1;
            const float preB = d0 + d1;

            const float sA = sigmf_(preA);                          // sig(i) / sig(f)
            const float sB = fmaf(aB, rcpf(1.f + ex2f(mB * preB)), cB); // tanh(g) / sig(o)

            const float oA = __shfl_xor_sync(0xffffffffu, sA, 16);
            const float oB = __shfl_xor_sync(0xffffffffu, sB, 16);

            const float f_ = hi ? sA : oA;
            const float i_ = hi ? oA : sA;
            const float g_ = hi ? oB : sB;
            const float o_ = hi ? sB : oB;

            c = fmaf(f_, c, i_ * g_);
            const float th = tanhf_(c);
            const float hn = o_ * th;

#pragma unroll
            for (int k = 0; k < 16; k++)
                h[k] = __shfl_sync(0xffffffffu, hn, k);

            const int t = tstart + st * tstep;
            if (!hi) outb[(size_t)t * 32] = hn;
        }
    }
}

// ---------------------------------------------------------------------------
// Upper layer-0 input projection with fused downsample: xu0[b][u][g] =
//   sum_c g_x[b][7+8u][c] * uWih0[g][c] + ub[0][g]
// ---------------------------------------------------------------------------
__global__ void __launch_bounds__(256) precompute_upper(
    const float* __restrict__ uWih0, const float* __restrict__ ub)
{
    __shared__ float W[4][32];
    __shared__ float bb4[4];
    if (threadIdx.x < 128) W[threadIdx.x >> 5][threadIdx.x & 31] = uWih0[threadIdx.x];
    if (threadIdx.x < 4) bb4[threadIdx.x] = ub[threadIdx.x];
    __syncthreads();

    const int b = blockIdx.x, u = threadIdx.x;
    const float* xr = g_x + ((size_t)b * Tn + 7 + 8 * u) * 32;
    float a0 = bb4[0], a1 = bb4[1], a2 = bb4[2], a3 = bb4[3];
#pragma unroll
    for (int i = 0; i < 32; i++) {
        const float xv = xr[i];
        a0 = fmaf(W[0][i], xv, a0);
        a1 = fmaf(W[1][i], xv, a1);
        a2 = fmaf(W[2][i], xv, a2);
        a3 = fmaf(W[3][i], xv, a3);
    }
    *(float4*)(g_xu0 + ((size_t)b * TU + u) * 4) = make_float4(a0, a1, a2, a3);
}

// ---------------------------------------------------------------------------
// Upper stack: 4 fused unidirectional LSTM layers with H=1, one thread per batch.
// ---------------------------------------------------------------------------
__global__ void __launch_bounds__(32) scan_upper(
    const float* __restrict__ uWih,  // [3][4]
    const float* __restrict__ uWhh,  // [4][4]
    const float* __restrict__ ub,    // [4][4]
    float* __restrict__ out)         // [B][256]
{
    const int b = blockIdx.x * 32 + threadIdx.x;
    float wih[3][4], whh[4][4], bu[4][4];
#pragma unroll
    for (int l = 0; l < 3; l++)
#pragma unroll
        for (int g = 0; g < 4; g++) wih[l][g] = uWih[l * 4 + g];
#pragma unroll
    for (int l = 0; l < 4; l++)
#pragma unroll
        for (int g = 0; g < 4; g++) {
            whh[l][g] = uWhh[l * 4 + g];
            bu[l][g] = ub[l * 4 + g];
        }

    float h[4] = {0.f, 0.f, 0.f, 0.f}, c[4] = {0.f, 0.f, 0.f, 0.f};
    const float4* xp = (const float4*)g_xu0 + (size_t)b * TU;

    for (int u = 0; u < TU; u++) {
        const float4 p = xp[u];
        // layer 0 (bias already folded into p)
        {
            const float pi = fmaf(whh[0][0], h[0], p.x);
            const float pf = fmaf(whh[0][1], h[0], p.y);
            const float pg = fmaf(whh[0][2], h[0], p.z);
            const float po = fmaf(whh[0][3], h[0], p.w);
            const float ii = sigmf_(pi), ff = sigmf_(pf), gg = tanhf_(pg), oo = sigmf_(po);
            c[0] = fmaf(ff, c[0], ii * gg);
            h[0] = oo * tanhf_(c[0]);
        }
#pragma unroll
        for (int l = 1; l < 4; l++) {
            const float pi = fmaf(wih[l - 1][0], h[l - 1], fmaf(whh[l][0], h[l], bu[l][0]));
            const float pf = fmaf(wih[l - 1][1], h[l - 1], fmaf(whh[l][1], h[l], bu[l][1]));
            const float pg = fmaf(wih[l - 1][2], h[l - 1], fmaf(whh[l][2], h[l], bu[l][2]));
            const float po = fmaf(wih[l - 1][3], h[l - 1], fmaf(whh[l][3], h[l], bu[l][3]));
            const float ii = sigmf_(pi), ff = sigmf_(pf), gg = tanhf_(pg), oo = sigmf_(po);
            c[l] = fmaf(ff, c[l], ii * gg);
            h[l] = oo * tanhf_(c[l]);
        }
        out[(size_t)b * TU + u] = h[3];
    }
}

// ---------------------------------------------------------------------------
extern "C" void kernel_launch(void* const* d_in, const int* in_sizes, int n_in,
                              void* d_out, int out_size)
{
    (void)in_sizes; (void)n_in; (void)out_size;
    const float* x0    = (const float*)d_in[0];  // [128,2048,24]
    const float* bWih0 = (const float*)d_in[1];  // [2,64,24]
    const float* bWih  = (const float*)d_in[2];  // [3,2,64,32]
    const float* bWhh  = (const float*)d_in[3];  // [4,2,64,16]
    const float* bb    = (const float*)d_in[4];  // [4,2,64]
    const float* uWih0 = (const float*)d_in[5];  // [4,32]
    const float* uWih  = (const float*)d_in[6];  // [3,4,1]
    const float* uWhh  = (const float*)d_in[7];  // [4,4,1]
    const float* ub    = (const float*)d_in[8];  // [4,4]

    const int nblk = (Bn * Tn) / 32;  // 8192

    for (int l = 0; l < 4; l++) {
        if (l == 0)
            precompute_bidir<24><<<nblk, 256>>>(x0, 0, bWih0, bb);
        else
            precompute_bidir<32><<<nblk, 256>>>(nullptr, 1,
                                                bWih + (size_t)(l - 1) * 2 * 64 * 32,
                                                bb + (size_t)l * 128);
        scan_bidir<<<dim3(Bn, 2), 32>>>(bWhh + (size_t)l * 2 * 64 * 16);
    }
    precompute_upper<<<Bn, 256>>>(uWih0, ub);
    scan_upper<<<Bn / 32, 32>>>(uWih, uWhh, ub, (float*)d_out);
}

// round 6
// speedup vs baseline: 1.7706x; 1.7706x over previous
#include <cuda_runtime.h>
#include <cstdint>

// ---------------------------------------------------------------------------
// pitch_predictor: 4x BiLSTM(H=16) over T=2048, B=128 -> downsample 7::8 ->
// 4x LSTM(H=1) over 256 steps. Latency-bound recurrences; one warp per chain.
// R5: shared-staged transposed weights in precompute (kills 32-line LDG replay
//     storm), MUFU.TANH activations with gate scale folded into weights.
// ---------------------------------------------------------------------------

#define Bn 128
#define Tn 2048
#define TU 256

// Scratch (device globals; no allocation allowed)
__device__ float g_xWp[2ull * Bn * Tn * 64];   // gate-permuted, prescaled input projections [dir][b][t][64]
__device__ float g_x[(size_t)Bn * Tn * 32];    // layer activations [b][t][32] (fwd 0..15, bwd 16..31)
__device__ float g_xu0[(size_t)Bn * TU * 4];   // upper layer-0 input projections (prescaled per gate)

// ---- activations: HW tanh (MUFU.TANH). sigmoid(x) = 0.5*tanh(0.5x)+0.5,
// with the 0.5 pre-activation scale folded into weights/bias upstream. ----
__device__ __forceinline__ float tanhf_a(float x) {
    float r; asm("tanh.approx.f32 %0, %1;" : "=f"(r) : "f"(x)); return r;
}

// gate rows within 64: [0,16)=i  [16,32)=f  [32,48)=g  [48,64)=o
// sigmoid rows (i,f,o) get weights/bias prescaled by 0.5; tanh rows (g) by 1.
__device__ __forceinline__ float gate_scale64(int row) {
    return (row < 32 || row >= 48) ? 0.5f : 1.0f;
}

// ---------------------------------------------------------------------------
// Precompute xW for one bidir layer, both directions, permuted gate layout:
//   p = 2*(r&31) + (r>>5)  for gate row r, so scan lane l reads float2 at
//   p=2l: (row l, row 32+l). Weights staged in shared, transposed WT[i][g]
//   so each thread owns one gate column -> conflict-free LDS, broadcast x.
// ---------------------------------------------------------------------------
template <int CIN>
__global__ void __launch_bounds__(256) precompute_bidir(
    const float* __restrict__ xin, int use_gx,
    const float* __restrict__ Wih,   // [2][64][CIN]
    const float* __restrict__ bias)  // [2][64]
{
    __shared__ float xs[32 * CIN];
    __shared__ float WT[CIN][128];
    __shared__ float bsh[128];

    // Stage weights: transpose + gate-permute + prescale. One-time scatter.
    for (int idx = threadIdx.x; idx < 128 * CIN; idx += 256) {
        const int r = idx / CIN;           // 0..127 = dir*64 + row
        const int i = idx - r * CIN;
        const int row = r & 63, dir = r >> 6;
        const int p = ((row & 31) << 1) | (row >> 5);
        WT[i][dir * 64 + p] = Wih[idx] * gate_scale64(row);
    }
    if (threadIdx.x < 128) {
        const int r = threadIdx.x;
        const int row = r & 63, dir = r >> 6;
        const int p = ((row & 31) << 1) | (row >> 5);
        bsh[dir * 64 + p] = bias[r] * gate_scale64(row);
    }
    const float* x = use_gx ? (const float*)g_x : xin;
    const int r0 = blockIdx.x * 32;        // 32 consecutive (b*T+t) rows
    {
        const float* src = x + (size_t)r0 * CIN;
        for (int i = threadIdx.x; i < 32 * CIN; i += 256) xs[i] = src[i];
    }
    __syncthreads();

    const int g = threadIdx.x & 127;       // gate column: dir*64 + p
    const int rh = threadIdx.x >> 7;       // row half 0/1
    const int dir = g >> 6, p = g & 63;

    float w[CIN];
#pragma unroll
    for (int i = 0; i < CIN; i++) w[i] = WT[i][g];   // conflict-free LDS
    const float bv = bsh[g];

    float* outd = g_xWp + (size_t)dir * Bn * Tn * 64;
#pragma unroll
    for (int rr = 0; rr < 16; rr++) {
        const int row = rh * 16 + rr;
        const float* xr = xs + row * CIN;
        float a = bv;
#pragma unroll
        for (int i = 0; i < CIN; i++) a = fmaf(w[i], xr[i], a);  // xs broadcast
        outd[(size_t)(r0 + row) * 64 + p] = a;       // coalesced
    }
}

// ---------------------------------------------------------------------------
// Bidirectional scan: one warp per (b, dir). Lane j<16 owns gates (i_j, g_j),
// lane j+16 owns (f_j, o_j). Pre-activations arrive prescaled (0.5 on sigmoid
// rows), so sigmoid = fma(0.5, tanh(pre), 0.5) and tanh = tanh(pre).
// ---------------------------------------------------------------------------
__global__ void __launch_bounds__(32) scan_bidir(const float* __restrict__ Whh /* [2][64][16] */)
{
    const int b = blockIdx.x;
    const int dir = blockIdx.y;
    const int lane = threadIdx.x;
    const int hi = lane >> 4;

    const float* wb = Whh + dir * 64 * 16;
    float WA[16], WB[16];
    const float sB_w = hi ? 0.5f : 1.0f;   // B gate: o (sig) vs g (tanh)
#pragma unroll
    for (int k = 0; k < 16; k++) {
        WA[k] = wb[lane * 16 + k] * 0.5f;          // rows 0-31: i/f, sigmoid
        WB[k] = wb[(32 + lane) * 16 + k] * sB_w;   // rows 32-63: g/o
    }
    const float aB = hi ? 0.5f : 1.0f;
    const float cBc = hi ? 0.5f : 0.0f;

    float h[16];
#pragma unroll
    for (int k = 0; k < 16; k++) h[k] = 0.f;
    float c = 0.f;

    const size_t chain = ((size_t)dir * Bn + b) * Tn;
    const float* pbase = g_xWp + chain * 64 + 2 * lane;
    const int tstart = dir ? (Tn - 1) : 0;
    const int tstep = dir ? -1 : 1;

    const int PF = 8;
    float2 buf[PF];
#pragma unroll
    for (int s = 0; s < PF; s++)
        buf[s] = *(const float2*)(pbase + (long)(tstart + s * tstep) * 64);

    float* outb = g_x + (size_t)b * Tn * 32 + dir * 16 + lane;  // lane<16 writes

    for (int it = 0; it < Tn; it += PF) {
#pragma unroll
        for (int s = 0; s < PF; s++) {
            const int st = it + s;
            const float2 xw = buf[s];
            const int pt = st + PF;
            if (pt < Tn)
                buf[s] = *(const float2*)(pbase + (long)(tstart + pt * tstep) * 64);

            // two 16-dots, split accumulators to halve FMA chain depth
            float a0 = xw.x, a1 = 0.f, d0 = xw.y, d1 = 0.f;
#pragma unroll
            for (int k = 0; k < 8; k++) {
                a0 = fmaf(WA[k], h[k], a0);
                d0 = fmaf(WB[k], h[k], d0);
            }
#pragma unroll
            for (int k = 8; k < 16; k++) {
                a1 = fmaf(WA[k], h[k], a1);
                d1 = fmaf(WB[k], h[k], d1);
            }
            const float preA = a0 + a1;
            const float preB = d0 + d1;

            const float sA = fmaf(0.5f, tanhf_a(preA), 0.5f);   // sig(i) / sig(f)
            const float sB = fmaf(aB, tanhf_a(preB), cBc);      // tanh(g) / sig(o)

            const float oA = __shfl_xor_sync(0xffffffffu, sA, 16);
            const float oB = __shfl_xor_sync(0xffffffffu, sB, 16);

            const float f_ = hi ? sA : oA;
            const float i_ = hi ? oA : sA;
            const float g_ = hi ? oB : sB;
            const float o_ = hi ? sB : oB;

            c = fmaf(f_, c, i_ * g_);
            const float hn = o_ * tanhf_a(c);

#pragma unroll
            for (int k = 0; k < 16; k++)
                h[k] = __shfl_sync(0xffffffffu, hn, k);

            const int t = tstart + st * tstep;
            if (!hi) outb[(size_t)t * 32] = hn;
        }
    }
}

// ---------------------------------------------------------------------------
// Upper layer-0 input projection with fused downsample (gate-prescaled):
//   xu0[b][u][g] = s_g * (sum_c g_x[b][7+8u][c] * uWih0[g][c] + ub[0][g])
// ---------------------------------------------------------------------------
__global__ void __launch_bounds__(256) precompute_upper(
    const float* __restrict__ uWih0, const float* __restrict__ ub)
{
    __shared__ float W[4][32];
    __shared__ float bb4[4];
    // gate order i,f,g,o: scales {0.5, 0.5, 1.0, 0.5}
    if (threadIdx.x < 128) {
        const int gg = threadIdx.x >> 5;
        const float s = (gg == 2) ? 1.0f : 0.5f;
        W[gg][threadIdx.x & 31] = uWih0[threadIdx.x] * s;
    }
    if (threadIdx.x < 4) {
        const float s = (threadIdx.x == 2) ? 1.0f : 0.5f;
        bb4[threadIdx.x] = ub[threadIdx.x] * s;
    }
    __syncthreads();

    const int b = blockIdx.x, u = threadIdx.x;
    const float* xr = g_x + ((size_t)b * Tn + 7 + 8 * u) * 32;
    float a0 = bb4[0], a1 = bb4[1], a2 = bb4[2], a3 = bb4[3];
#pragma unroll
    for (int i = 0; i < 32; i++) {
        const float xv = xr[i];
        a0 = fmaf(W[0][i], xv, a0);
        a1 = fmaf(W[1][i], xv, a1);
        a2 = fmaf(W[2][i], xv, a2);
        a3 = fmaf(W[3][i], xv, a3);
    }
    *(float4*)(g_xu0 + ((size_t)b * TU + u) * 4) = make_float4(a0, a1, a2, a3);
}

// ---------------------------------------------------------------------------
// Upper stack: 4 fused unidirectional LSTM layers with H=1, one thread/batch.
// ---------------------------------------------------------------------------
__global__ void __launch_bounds__(32) scan_upper(
    const float* __restrict__ uWih,  // [3][4]
    const float* __restrict__ uWhh,  // [4][4]
    const float* __restrict__ ub,    // [4][4]
    float* __restrict__ out)         // [B][256]
{
    const int b = blockIdx.x * 32 + threadIdx.x;
    float wih[3][4], whh[4][4], bu[4][4];
#pragma unroll
    for (int l = 0; l < 3; l++)
#pragma unroll
        for (int g = 0; g < 4; g++) {
            const float s = (g == 2) ? 1.0f : 0.5f;
            wih[l][g] = uWih[l * 4 + g] * s;
        }
#pragma unroll
    for (int l = 0; l < 4; l++)
#pragma unroll
        for (int g = 0; g < 4; g++) {
            const float s = (g == 2) ? 1.0f : 0.5f;
            whh[l][g] = uWhh[l * 4 + g] * s;
            bu[l][g] = ub[l * 4 + g] * s;
        }

    float h[4] = {0.f, 0.f, 0.f, 0.f}, c[4] = {0.f, 0.f, 0.f, 0.f};
    const float4* xp = (const float4*)g_xu0 + (size_t)b * TU;

    for (int u = 0; u < TU; u++) {
        const float4 p = xp[u];
        // layer 0 (scaled bias already folded into p)
        {
            const float pi = fmaf(whh[0][0], h[0], p.x);
            const float pf = fmaf(whh[0][1], h[0], p.y);
            const float pg = fmaf(whh[0][2], h[0], p.z);
            const float po = fmaf(whh[0][3], h[0], p.w);
            const float ii = fmaf(0.5f, tanhf_a(pi), 0.5f);
            const float ff = fmaf(0.5f, tanhf_a(pf), 0.5f);
            const float gg = tanhf_a(pg);
            const float oo = fmaf(0.5f, tanhf_a(po), 0.5f);
            c[0] = fmaf(ff, c[0], ii * gg);
            h[0] = oo * tanhf_a(c[0]);
        }
#pragma unroll
        for (int l = 1; l < 4; l++) {
            const float pi = fmaf(wih[l - 1][0], h[l - 1], fmaf(whh[l][0], h[l], bu[l][0]));
            const float pf = fmaf(wih[l - 1][1], h[l - 1], fmaf(whh[l][1], h[l], bu[l][1]));
            const float pg = fmaf(wih[l - 1][2], h[l - 1], fmaf(whh[l][2], h[l], bu[l][2]));
            const float po = fmaf(wih[l - 1][3], h[l - 1], fmaf(whh[l][3], h[l], bu[l][3]));
            const float ii = fmaf(0.5f, tanhf_a(pi), 0.5f);
            const float ff = fmaf(0.5f, tanhf_a(pf), 0.5f);
            const float gg = tanhf_a(pg);
            const float oo = fmaf(0.5f, tanhf_a(po), 0.5f);
            c[l] = fmaf(ff, c[l], ii * gg);
            h[l] = oo * tanhf_a(c[l]);
        }
        out[(size_t)b * TU + u] = h[3];
    }
}

// ---------------------------------------------------------------------------
extern "C" void kernel_launch(void* const* d_in, const int* in_sizes, int n_in,
                              void* d_out, int out_size)
{
    (void)in_sizes; (void)n_in; (void)out_size;
    const float* x0    = (const float*)d_in[0];  // [128,2048,24]
    const float* bWih0 = (const float*)d_in[1];  // [2,64,24]
    const float* bWih  = (const float*)d_in[2];  // [3,2,64,32]
    const float* bWhh  = (const float*)d_in[3];  // [4,2,64,16]
    const float* bb    = (const float*)d_in[4];  // [4,2,64]
    const float* uWih0 = (const float*)d_in[5];  // [4,32]
    const float* uWih  = (const float*)d_in[6];  // [3,4,1]
    const float* uWhh  = (const float*)d_in[7];  // [4,4,1]
    const float* ub    = (const float*)d_in[8];  // [4,4]

    const int nblk = (Bn * Tn) / 32;  // 8192

    for (int l = 0; l < 4; l++) {
        if (l == 0)
            precompute_bidir<24><<<nblk, 256>>>(x0, 0, bWih0, bb);
        else
            precompute_bidir<32><<<nblk, 256>>>(nullptr, 1,
                                                bWih + (size_t)(l - 1) * 2 * 64 * 32,
                                                bb + (size_t)l * 128);
        scan_bidir<<<dim3(Bn, 2), 32>>>(bWhh + (size_t)l * 2 * 64 * 16);
    }
    precompute_upper<<<Bn, 256>>>(uWih0, ub);
    scan_upper<<<Bn / 32, 32>>>(uWih, uWhh, ub, (float*)d_out);
}